// round 6
// baseline (speedup 1.0000x reference)
#include <cuda_runtime.h>
#include <cuda_bf16.h>

#define N_NODES 100000
#define N_EDGES 3200000
#define F_IN 8
#define F_HID 64
#define E4 (N_EDGES / 4)

// Scratch: __device__ globals (GPU DRAM; allocation-free rule)
__device__ float g_deg[N_NODES];
__device__ float g_dinv[N_NODES];
__device__ __align__(16) float g_xs[N_NODES * F_IN];     // dinv[i] * x[i]
__device__ __align__(16) float g_acc1[N_NODES * F_IN];   // sum_{edges into c} w * xs[r]
__device__ float g_sd[N_NODES];                          // dinv[i] * s[i]
__device__ float g_acc2[N_NODES];                        // sum_{edges into c} w * sd[r]

// ---------------------------------------------------------------------------
// 1) deg init: self-loop contributes weight 1
__global__ void k_deg_init() {
    int i = blockIdx.x * blockDim.x + threadIdx.x;
    if (i < N_NODES) g_deg[i] = 1.0f;
}

// 2) deg accumulate, 4 edges/thread: deg[col] += w
__global__ void k_deg_acc4(const int* __restrict__ ei, const float* __restrict__ w) {
    int t = blockIdx.x * blockDim.x + threadIdx.x;
    if (t >= E4) return;
    int4   c4 = ((const int4*)(ei + N_EDGES))[t];
    float4 w4 = ((const float4*)w)[t];
    atomicAdd(&g_deg[c4.x], w4.x);
    atomicAdd(&g_deg[c4.y], w4.y);
    atomicAdd(&g_deg[c4.z], w4.z);
    atomicAdd(&g_deg[c4.w], w4.w);
}

// 3) dinv = rsqrt(deg); xs = dinv*x; zero acc1 & acc2 (fused init)
__global__ void k_dinv_xs(const float* __restrict__ x) {
    int i = blockIdx.x * blockDim.x + threadIdx.x;
    if (i >= N_NODES) return;
    float dv = rsqrtf(g_deg[i]);
    g_dinv[i] = dv;
    const float4* xr = (const float4*)(x + (size_t)i * F_IN);
    float4 a = xr[0], b = xr[1];
    float4* o = (float4*)(g_xs + (size_t)i * F_IN);
    o[0] = make_float4(a.x * dv, a.y * dv, a.z * dv, a.w * dv);
    o[1] = make_float4(b.x * dv, b.y * dv, b.z * dv, b.w * dv);
    float4 z = make_float4(0.f, 0.f, 0.f, 0.f);
    float4* ac = (float4*)(g_acc1 + (size_t)i * F_IN);
    ac[0] = z; ac[1] = z;
    g_acc2[i] = 0.0f;
}

// vectorized fire-and-forget float4 reduction (sm_103a)
__device__ __forceinline__ void red_add_v4(float* p, float a, float b, float c, float d) {
    asm volatile("red.global.add.v4.f32 [%0], {%1,%2,%3,%4};"
                 :: "l"(p), "f"(a), "f"(b), "f"(c), "f"(d) : "memory");
}

__device__ __forceinline__ void l1_edge(int r, int c, float we) {
    const float4* xr = (const float4*)(g_xs + (size_t)r * F_IN);
    float4 a = xr[0], b = xr[1];
    float* dst = g_acc1 + (size_t)c * F_IN;
    red_add_v4(dst,     we * a.x, we * a.y, we * a.z, we * a.w);
    red_add_v4(dst + 4, we * b.x, we * b.y, we * b.z, we * b.w);
}

// 4) layer-1 edge pass, 4 edges/thread: acc1[c] += w * xs[r]
__global__ void k_layer1_edges4(const int* __restrict__ ei, const float* __restrict__ w) {
    int t = blockIdx.x * blockDim.x + threadIdx.x;
    if (t >= E4) return;
    int4   r4 = ((const int4*)ei)[t];
    int4   c4 = ((const int4*)(ei + N_EDGES))[t];
    float4 w4 = ((const float4*)w)[t];
    l1_edge(r4.x, c4.x, w4.x);
    l1_edge(r4.y, c4.y, w4.y);
    l1_edge(r4.z, c4.z, w4.z);
    l1_edge(r4.w, c4.w, w4.w);
}

// 5) node MLP: a = dinv*acc1 + dinv^2*x ; h = relu(a@W1+b1); s = h@W2; sd = dinv*s
__global__ void k_node_mlp(const float* __restrict__ x,
                           const float* __restrict__ W1,
                           const float* __restrict__ b1,
                           const float* __restrict__ W2) {
    __shared__ float sW1[F_IN * F_HID];   // [k][f]: sW1[k*64+f]
    __shared__ float sb1[F_HID];
    __shared__ float sW2[F_HID];
    for (int t = threadIdx.x; t < F_IN * F_HID; t += blockDim.x) sW1[t] = W1[t];
    for (int t = threadIdx.x; t < F_HID; t += blockDim.x) { sb1[t] = b1[t]; sW2[t] = W2[t]; }
    __syncthreads();

    int i = blockIdx.x * blockDim.x + threadIdx.x;
    if (i >= N_NODES) return;

    float dv = g_dinv[i];
    float dv2 = dv * dv;
    const float4* ac = (const float4*)(g_acc1 + (size_t)i * F_IN);
    const float4* xr = (const float4*)(x + (size_t)i * F_IN);
    float4 a0 = ac[0], a1 = ac[1], x0 = xr[0], x1 = xr[1];
    float a[F_IN];
    a[0] = dv * a0.x + dv2 * x0.x;  a[1] = dv * a0.y + dv2 * x0.y;
    a[2] = dv * a0.z + dv2 * x0.z;  a[3] = dv * a0.w + dv2 * x0.w;
    a[4] = dv * a1.x + dv2 * x1.x;  a[5] = dv * a1.y + dv2 * x1.y;
    a[6] = dv * a1.z + dv2 * x1.z;  a[7] = dv * a1.w + dv2 * x1.w;

    float s = 0.0f;
    #pragma unroll 8
    for (int f = 0; f < F_HID; f++) {
        float acc = sb1[f];
        #pragma unroll
        for (int k = 0; k < F_IN; k++) acc = fmaf(a[k], sW1[k * F_HID + f], acc);
        s += fmaxf(acc, 0.0f) * sW2[f];
    }
    g_sd[i] = dv * s;
}

// 6) layer-2 edge pass, 4 edges/thread: acc2[c] += w * sd[r]
__global__ void k_layer2_edges4(const int* __restrict__ ei, const float* __restrict__ w) {
    int t = blockIdx.x * blockDim.x + threadIdx.x;
    if (t >= E4) return;
    int4   r4 = ((const int4*)ei)[t];
    int4   c4 = ((const int4*)(ei + N_EDGES))[t];
    float4 w4 = ((const float4*)w)[t];
    float s0 = g_sd[r4.x], s1 = g_sd[r4.y], s2 = g_sd[r4.z], s3 = g_sd[r4.w];
    atomicAdd(&g_acc2[c4.x], w4.x * s0);
    atomicAdd(&g_acc2[c4.y], w4.y * s1);
    atomicAdd(&g_acc2[c4.z], w4.z * s2);
    atomicAdd(&g_acc2[c4.w], w4.w * s3);
}

// 7) epilogue: out = b2 + dinv * (acc2 + sd)   (plain stores to d_out)
__global__ void k_out(const float* __restrict__ b2, float* __restrict__ out) {
    int i = blockIdx.x * blockDim.x + threadIdx.x;
    if (i < N_NODES) out[i] = b2[0] + g_dinv[i] * (g_acc2[i] + g_sd[i]);
}

extern "C" void kernel_launch(void* const* d_in, const int* in_sizes, int n_in,
                              void* d_out, int out_size) {
    const float* x  = (const float*)d_in[0];
    const int*   ei = (const int*)d_in[1];     // int32 (JAX x64 disabled)
    const float* w  = (const float*)d_in[2];
    const float* W1 = (const float*)d_in[3];
    const float* b1 = (const float*)d_in[4];
    const float* W2 = (const float*)d_in[5];
    const float* b2 = (const float*)d_in[6];
    float* out = (float*)d_out;

    const int TB = 256;
    const int gridN  = (N_NODES + TB - 1) / TB;
    const int gridE4 = (E4 + TB - 1) / TB;

    k_deg_init<<<gridN, TB>>>();
    k_deg_acc4<<<gridE4, TB>>>(ei, w);
    k_dinv_xs<<<gridN, TB>>>(x);
    k_layer1_edges4<<<gridE4, TB>>>(ei, w);
    k_node_mlp<<<gridN, TB>>>(x, W1, b1, W2);
    k_layer2_edges4<<<gridE4, TB>>>(ei, w);
    k_out<<<gridN, TB>>>(b2, out);
}